// round 3
// baseline (speedup 1.0000x reference)
#include <cuda_runtime.h>

// Problem constants
#define Bq   512
#define Tq   256
#define Fq   256
#define Hq   512
#define KTOT 768          // Hq + Fq  (fused [h | x_t] GEMM)
#define NG   2048         // 4*Hq gate columns

// Step-kernel tiling
#define BM      64        // batch rows per block
#define BJ      32        // hidden units per block
#define BCOLS   128       // gate columns per block = 4*BJ
#define BK      16        // K-tile
#define AP      68        // padded A smem row (floats), multiple of 4 for float4
#define NTHREADS 128

// Persistent state (device globals: allocation-free per harness rules)
__device__ float g_h[2][Bq * Hq];
__device__ float g_c[Bq * Hq];

__device__ __forceinline__ float fsig(float x)  { return 1.0f / (1.0f + __expf(-x)); }
__device__ __forceinline__ float ftanh(float x) { return 2.0f / (1.0f + __expf(-2.0f * x)) - 1.0f; }

__global__ void zero_state_kernel() {
    int i = blockIdx.x * blockDim.x + threadIdx.x;
    const int n = Bq * Hq;
    for (; i < n; i += gridDim.x * blockDim.x) {
        g_h[0][i] = 0.0f;
        g_c[i]    = 0.0f;
    }
}

__device__ __forceinline__ void prefetch_tile(
    int k0, int t, int m0, int lm, int kq, int wr,
    const float* __restrict__ h_in, const float* __restrict__ x,
    const float* __restrict__ Whh,  const float* __restrict__ Wih,
    float4& a0, float4& a1, float4& w0, float4& w1, float4& w2, float4& w3)
{
    // A operand: rows = batch, cols = [h (0..511) | x_t (512..767)]
    const float* asrc = (k0 < Hq)
        ? h_in + (size_t)(m0 + lm) * Hq + k0 + kq * 8
        : x    + (size_t)(m0 + lm) * (Tq * Fq) + (size_t)t * Fq + (k0 - Hq) + kq * 8;
    a0 = *(const float4*)asrc;
    a1 = *(const float4*)(asrc + 4);

    // W operand: row wr of [W_hh | W_ih]
    const float* wsrc = (k0 < Hq)
        ? Whh + (size_t)wr * Hq + k0
        : Wih + (size_t)wr * Fq + (k0 - Hq);
    w0 = *(const float4*)(wsrc);
    w1 = *(const float4*)(wsrc + 4);
    w2 = *(const float4*)(wsrc + 8);
    w3 = *(const float4*)(wsrc + 12);
}

// One LSTM timestep: gates = [h|x_t] @ [W_hh|W_ih]^T + b_ih + b_hh, then
// elementwise LSTM update fused into the epilogue.
// Grid: (NG/BCOLS, Bq/BM) = (16, 8) = 128 blocks, 128 threads each.
// Column layout inside a block (c in [0,128)): gate g = c&3, hidden j = j0 + (c>>2)
// => each thread (owning 8 consecutive c) holds i,f,g,o for 2 hidden units.
// Smem is double-buffered: 1 BAR.SYNC per K-tile; smem stores of tile k+1
// overlap FMA on tile k.
__global__ __launch_bounds__(NTHREADS)
void lstm_step_kernel(const float* __restrict__ x,
                      const float* __restrict__ Wih,
                      const float* __restrict__ Whh,
                      const float* __restrict__ bih,
                      const float* __restrict__ bhh,
                      int t)
{
    const float* __restrict__ h_in  = g_h[t & 1];
    float* __restrict__       h_out = g_h[(t + 1) & 1];

    __shared__ float As[2][BK][AP];      // A tile, transposed: As[buf][k][m]
    __shared__ float Ws[2][BK][BCOLS];   // W tile, transposed: Ws[buf][k][c]

    const int tid = threadIdx.x;
    const int tr  = tid >> 4;   // 0..7  : row group (8 rows each)
    const int tc  = tid & 15;   // 0..15 : col group (8 cols each)
    const int m0  = blockIdx.y * BM;
    const int j0  = blockIdx.x * BJ;

    // Loader roles
    const int lm = tid >> 1;    // 0..63 : A row to load
    const int kq = tid & 1;     // which 8-k half
    const int wc = tid;         // 0..127: W column to load
    const int wr = (wc & 3) * Hq + j0 + (wc >> 2);   // global weight row for col wc

    // Accumulators initialized with combined bias (b_ih + b_hh)
    float acc[8][8];
    #pragma unroll
    for (int u = 0; u < 8; u++) {
        const int c   = tc * 8 + u;
        const int row = (c & 3) * Hq + j0 + (c >> 2);
        const float bias = bih[row] + bhh[row];
        #pragma unroll
        for (int r = 0; r < 8; r++) acc[r][u] = bias;
    }

    const int NT = KTOT / BK;   // 48 K-tiles
    float4 pa0, pa1, pw0, pw1, pw2, pw3;

    // Prologue: load tile 0 into buffer 0
    prefetch_tile(0, t, m0, lm, kq, wr, h_in, x, Whh, Wih, pa0, pa1, pw0, pw1, pw2, pw3);
    {
        const float av[8] = {pa0.x, pa0.y, pa0.z, pa0.w, pa1.x, pa1.y, pa1.z, pa1.w};
        #pragma unroll
        for (int e = 0; e < 8; e++) As[0][kq * 8 + e][lm] = av[e];
        const float wv[16] = {pw0.x, pw0.y, pw0.z, pw0.w, pw1.x, pw1.y, pw1.z, pw1.w,
                              pw2.x, pw2.y, pw2.z, pw2.w, pw3.x, pw3.y, pw3.z, pw3.w};
        #pragma unroll
        for (int e = 0; e < 16; e++) Ws[0][e][wc] = wv[e];
    }
    __syncthreads();

    for (int kt = 0; kt < NT; kt++) {
        const int cur = kt & 1;
        const int nxt = cur ^ 1;

        // Issue global prefetch of next tile early (hides L2 latency under FMAs)
        const bool have_next = (kt + 1 < NT);
        if (have_next)
            prefetch_tile((kt + 1) * BK, t, m0, lm, kq, wr, h_in, x, Whh, Wih,
                          pa0, pa1, pw0, pw1, pw2, pw3);

        // 16 x (8x8) FMA on current buffer
        #pragma unroll
        for (int k = 0; k < BK; k++) {
            const float4 a0 = *(const float4*)&As[cur][k][tr * 8];
            const float4 a1 = *(const float4*)&As[cur][k][tr * 8 + 4];
            const float4 w0 = *(const float4*)&Ws[cur][k][tc * 8];
            const float4 w1 = *(const float4*)&Ws[cur][k][tc * 8 + 4];
            const float av[8] = {a0.x, a0.y, a0.z, a0.w, a1.x, a1.y, a1.z, a1.w};
            const float wv[8] = {w0.x, w0.y, w0.z, w0.w, w1.x, w1.y, w1.z, w1.w};
            #pragma unroll
            for (int r = 0; r < 8; r++)
                #pragma unroll
                for (int u = 0; u < 8; u++)
                    acc[r][u] += av[r] * wv[u];
        }

        // Store next tile into the other buffer, then one barrier
        if (have_next) {
            const float av[8] = {pa0.x, pa0.y, pa0.z, pa0.w, pa1.x, pa1.y, pa1.z, pa1.w};
            #pragma unroll
            for (int e = 0; e < 8; e++) As[nxt][kq * 8 + e][lm] = av[e];
            const float wv[16] = {pw0.x, pw0.y, pw0.z, pw0.w, pw1.x, pw1.y, pw1.z, pw1.w,
                                  pw2.x, pw2.y, pw2.z, pw2.w, pw3.x, pw3.y, pw3.z, pw3.w};
            #pragma unroll
            for (int e = 0; e < 16; e++) Ws[nxt][e][wc] = wv[e];
            __syncthreads();
        }
    }

    // Epilogue: acc[r][d*4+g] holds gate g for hidden unit j0 + tc*2 + d.
    #pragma unroll
    for (int r = 0; r < 8; r++) {
        const int m = m0 + tr * 8 + r;
        #pragma unroll
        for (int d = 0; d < 2; d++) {
            const int j = j0 + tc * 2 + d;
            const size_t idx = (size_t)m * Hq + j;
            const float ig = fsig (acc[r][d * 4 + 0]);
            const float fg = fsig (acc[r][d * 4 + 1]);
            const float gg = ftanh(acc[r][d * 4 + 2]);
            const float og = fsig (acc[r][d * 4 + 3]);
            const float cn = fg * g_c[idx] + ig * gg;
            g_c[idx]   = cn;
            h_out[idx] = og * ftanh(cn);
        }
    }
}

// out[b] = h_final[b,:] . W_out[0,:] + b_out[0]
__global__ void head_kernel(const float* __restrict__ Wout,
                            const float* __restrict__ bout,
                            float* __restrict__ out)
{
    const int b = blockIdx.x;
    const float* hrow = g_h[Tq & 1] + (size_t)b * Hq;   // T even -> final h in buffer 0
    float s = 0.0f;
    for (int k = threadIdx.x; k < Hq; k += blockDim.x)
        s += hrow[k] * Wout[k];
    __shared__ float red[32];
    #pragma unroll
    for (int o = 16; o; o >>= 1) s += __shfl_down_sync(0xffffffffu, s, o);
    if ((threadIdx.x & 31) == 0) red[threadIdx.x >> 5] = s;
    __syncthreads();
    if (threadIdx.x == 0)
        out[b] = red[0] + red[1] + red[2] + red[3] + bout[0];
}

extern "C" void kernel_launch(void* const* d_in, const int* in_sizes, int n_in,
                              void* d_out, int out_size)
{
    (void)in_sizes; (void)n_in; (void)out_size;
    const float* x    = (const float*)d_in[0];   // [B, T, F]
    const float* Wih  = (const float*)d_in[1];   // [4H, F]
    const float* Whh  = (const float*)d_in[2];   // [4H, H]
    const float* bih  = (const float*)d_in[3];   // [4H]
    const float* bhh  = (const float*)d_in[4];   // [4H]
    const float* Wout = (const float*)d_in[5];   // [O, H]
    const float* bout = (const float*)d_in[6];   // [O]
    float* out = (float*)d_out;                  // [B, O]

    zero_state_kernel<<<256, 256>>>();

    dim3 grid(NG / BCOLS, Bq / BM);              // (16, 8) = 128 blocks
    for (int t = 0; t < Tq; t++)
        lstm_step_kernel<<<grid, NTHREADS>>>(x, Wih, Whh, bih, bhh, t);

    head_kernel<<<Bq, 128>>>(Wout, bout, out);
}